// round 1
// baseline (speedup 1.0000x reference)
#include <cuda_runtime.h>

#define DIM 85
#define ROWS 128          // rows per block tile
#define THREADS 128
#define MAX_BLOCKS 8192

__device__ float g_partials[MAX_BLOCKS];

__global__ __launch_bounds__(THREADS)
void qfd_stage1(const float* __restrict__ in, const float* __restrict__ tg, int B)
{
    __shared__ float s[ROWS * DIM];          // 43520 B, conflict-free at stride 85
    __shared__ float warp_part[THREADS / 32];

    const int rows = min(ROWS, B - (int)blockIdx.x * ROWS);
    const size_t base = (size_t)blockIdx.x * ROWS * DIM;

    if (rows == ROWS) {
        // Full tile: vectorized coalesced load; tile base is 16B aligned (43520B multiple)
        const float4* in4 = (const float4*)(in + base);
        const float4* tg4 = (const float4*)(tg + base);
        float4* s4 = (float4*)s;
        const int n4 = ROWS * DIM / 4;       // 2720
        for (int i = threadIdx.x; i < n4; i += THREADS) {
            float4 a = in4[i];
            float4 b = tg4[i];
            float4 d;
            d.x = fabsf(a.x - b.x);
            d.y = fabsf(a.y - b.y);
            d.z = fabsf(a.z - b.z);
            d.w = fabsf(a.w - b.w);
            s4[i] = d;
        }
    } else {
        const int elems = rows * DIM;
        for (int i = threadIdx.x; i < elems; i += THREADS)
            s[i] = fabsf(in[base + i] - tg[base + i]);
    }
    __syncthreads();

    // Per-row O(D) scan exploiting Toeplitz A:  q = S^2 - (2/85) * U
    float q = 0.0f;
    if (threadIdx.x < rows) {
        const float* r = s + threadIdx.x * DIM;
        float P  = 0.0f;   // prefix sum of d
        float Qn = 0.0f;   // negated prefix sum of k*d_k
        float U  = 0.0f;
#pragma unroll
        for (int k = 0; k < DIM; k++) {
            float d = r[k];
            // U += d * (k*P - Q), with P,Q over i<k  (k is an immediate after unroll)
            U  = fmaf(d, fmaf((float)k, P, Qn), U);
            P += d;
            Qn = fmaf(-(float)k, d, Qn);
        }
        q = fmaf(P, P, -(2.0f / (float)DIM) * U);
    }

    // Deterministic block reduction
    for (int o = 16; o; o >>= 1)
        q += __shfl_down_sync(0xffffffffu, q, o);
    if ((threadIdx.x & 31) == 0)
        warp_part[threadIdx.x >> 5] = q;
    __syncthreads();
    if (threadIdx.x == 0) {
        float t = 0.0f;
#pragma unroll
        for (int i = 0; i < THREADS / 32; i++)
            t += warp_part[i];
        g_partials[blockIdx.x] = t;
    }
}

__global__ __launch_bounds__(256)
void qfd_stage2(float* out, int nblocks)
{
    __shared__ double sd[256];
    double acc = 0.0;
    for (int i = threadIdx.x; i < nblocks; i += 256)
        acc += (double)g_partials[i];
    sd[threadIdx.x] = acc;
    __syncthreads();
    for (int o = 128; o; o >>= 1) {
        if (threadIdx.x < o) sd[threadIdx.x] += sd[threadIdx.x + o];
        __syncthreads();
    }
    if (threadIdx.x == 0)
        out[0] = (float)(0.1 * sd[0]);
}

extern "C" void kernel_launch(void* const* d_in, const int* in_sizes, int n_in,
                              void* d_out, int out_size)
{
    const float* in = (const float*)d_in[0];
    const float* tg = (const float*)d_in[1];
    float* out = (float*)d_out;

    int B = in_sizes[0] / DIM;                       // 262144
    int nblocks = (B + ROWS - 1) / ROWS;             // 2048
    if (nblocks > MAX_BLOCKS) nblocks = MAX_BLOCKS;  // safety (not expected)

    qfd_stage1<<<nblocks, THREADS>>>(in, tg, B);
    qfd_stage2<<<1, 256>>>(out, nblocks);
}

// round 2
// speedup vs baseline: 1.0959x; 1.0959x over previous
#include <cuda_runtime.h>

#define DIM 85
#define ROWS 128          // rows per block tile
#define THREADS 128
#define NBLOCKS 2048      // 262144 / 128  (B is fixed by the problem)
#define N4 (ROWS * DIM / 4)        // 2720 float4 per tile
#define LOAD_ITERS ((N4 + THREADS - 1) / THREADS)   // 22

__device__ float g_partials[NBLOCKS];
__device__ int   g_count = 0;      // self-resetting arrival counter

__global__ __launch_bounds__(THREADS)
void qfd_fused(const float* __restrict__ in, const float* __restrict__ tg,
               float* __restrict__ out, int nblocks)
{
    __shared__ float s[ROWS * DIM];          // 43520 B; stride-85 scan is conflict-free
    __shared__ float warp_part[THREADS / 32];
    __shared__ bool  s_is_last;

    const size_t base = (size_t)blockIdx.x * (ROWS * DIM);

    // ---- Tile load: fully unrolled, front-batched LDG.128 for max MLP ----
    {
        const float4* __restrict__ in4 = (const float4*)(in + base);
        const float4* __restrict__ tg4 = (const float4*)(tg + base);
        float4* s4 = (float4*)s;
#pragma unroll
        for (int j = 0; j < LOAD_ITERS; j++) {
            int i = threadIdx.x + j * THREADS;
            if (i < N4) {
                float4 a = in4[i];
                float4 b = tg4[i];
                float4 d;
                d.x = fabsf(a.x - b.x);
                d.y = fabsf(a.y - b.y);
                d.z = fabsf(a.z - b.z);
                d.w = fabsf(a.w - b.w);
                s4[i] = d;
            }
        }
    }
    __syncthreads();

    // ---- Per-row O(D) Toeplitz scan:  q = S^2 - (2/85) * U ----
    // U = sum_{i<j} (j-i) d_i d_j, built from prefix sums P, Q.
    float q;
    {
        const float* r = s + threadIdx.x * DIM;
        float P  = 0.0f;   // prefix sum of d
        float Qn = 0.0f;   // negated prefix sum of k*d_k
        float U  = 0.0f;
#pragma unroll
        for (int k = 0; k < DIM; k++) {
            float d = r[k];
            U  = fmaf(d, fmaf((float)k, P, Qn), U);
            P += d;
            Qn = fmaf(-(float)k, d, Qn);
        }
        q = fmaf(P, P, -(2.0f / (float)DIM) * U);
    }

    // ---- Deterministic block reduction ----
    for (int o = 16; o; o >>= 1)
        q += __shfl_down_sync(0xffffffffu, q, o);
    if ((threadIdx.x & 31) == 0)
        warp_part[threadIdx.x >> 5] = q;
    __syncthreads();
    if (threadIdx.x == 0) {
        float t = 0.0f;
#pragma unroll
        for (int i = 0; i < THREADS / 32; i++)
            t += warp_part[i];
        g_partials[blockIdx.x] = t;
        __threadfence();                          // partial visible before arrival
        int old = atomicAdd(&g_count, 1);
        s_is_last = (old == nblocks - 1);
    }
    __syncthreads();

    // ---- Last-arriving block does the final deterministic reduce ----
    if (s_is_last) {
        __shared__ double sd[THREADS];
        double acc = 0.0;
#pragma unroll
        for (int j = 0; j < NBLOCKS / THREADS; j++)     // 16 iterations, fixed order
            acc += (double)g_partials[threadIdx.x + j * THREADS];
        sd[threadIdx.x] = acc;
        __syncthreads();
        for (int o = THREADS / 2; o; o >>= 1) {
            if (threadIdx.x < o) sd[threadIdx.x] += sd[threadIdx.x + o];
            __syncthreads();
        }
        if (threadIdx.x == 0) {
            out[0] = (float)(0.1 * sd[0]);
            g_count = 0;                          // self-reset for next replay
        }
    }
}

extern "C" void kernel_launch(void* const* d_in, const int* in_sizes, int n_in,
                              void* d_out, int out_size)
{
    const float* in = (const float*)d_in[0];
    const float* tg = (const float*)d_in[1];
    float* out = (float*)d_out;

    // B = 262144, D = 85 fixed by the problem; grid covers exactly B rows.
    qfd_fused<<<NBLOCKS, THREADS>>>(in, tg, out, NBLOCKS);
}

// round 3
// speedup vs baseline: 1.2230x; 1.1160x over previous
#include <cuda_runtime.h>

#define DIM 85
#define ROWS 128                   // rows per block tile
#define THREADS 256                // 128 scanners + all 256 load
#define NBLOCKS 2048               // 262144 / 128  (B fixed by the problem)
#define N4 (ROWS * DIM / 4)        // 2720 float4 per tile
#define LOAD_ITERS ((N4 + THREADS - 1) / THREADS)   // 11

__device__ float g_partials[NBLOCKS];
__device__ int   g_count = 0;      // self-resetting arrival counter

__global__ __launch_bounds__(THREADS)
void qfd_fused(const float* __restrict__ in, const float* __restrict__ tg,
               float* __restrict__ out, int nblocks)
{
    __shared__ float s[ROWS * DIM];          // 43520 B; stride-85 scan conflict-free
    __shared__ float warp_part[4];           // partials from the 4 scanning warps
    __shared__ bool  s_is_last;

    const size_t base = (size_t)blockIdx.x * (ROWS * DIM);

    // ---- Tile load: all 256 threads, fully unrolled, front-batched LDG.128 ----
    {
        const float4* __restrict__ in4 = (const float4*)(in + base);
        const float4* __restrict__ tg4 = (const float4*)(tg + base);
        float4* s4 = (float4*)s;
#pragma unroll
        for (int j = 0; j < LOAD_ITERS; j++) {
            int i = threadIdx.x + j * THREADS;
            if (i < N4) {
                float4 a = in4[i];
                float4 b = tg4[i];
                float4 d;
                d.x = fabsf(a.x - b.x);
                d.y = fabsf(a.y - b.y);
                d.z = fabsf(a.z - b.z);
                d.w = fabsf(a.w - b.w);
                s4[i] = d;
            }
        }
    }
    __syncthreads();

    // ---- Per-row O(D) Toeplitz scan (threads 0..127):  q = S^2 - (2/85)*U ----
    // U = sum_{i<j} (j-i) d_i d_j, via prefix sums P (of d) and Qn (of -k*d_k).
    if (threadIdx.x < ROWS) {
        const float* r = s + threadIdx.x * DIM;
        float P  = 0.0f;
        float Qn = 0.0f;
        float U  = 0.0f;
#pragma unroll
        for (int k = 0; k < DIM; k++) {
            float d = r[k];
            U  = fmaf(d, fmaf((float)k, P, Qn), U);
            P += d;
            Qn = fmaf(-(float)k, d, Qn);
        }
        float q = fmaf(P, P, -(2.0f / (float)DIM) * U);

        // warp-level deterministic reduce (4 scanning warps)
        for (int o = 16; o; o >>= 1)
            q += __shfl_down_sync(0xffffffffu, q, o);
        if ((threadIdx.x & 31) == 0)
            warp_part[threadIdx.x >> 5] = q;
    }
    __syncthreads();

    if (threadIdx.x == 0) {
        float t = warp_part[0] + warp_part[1] + warp_part[2] + warp_part[3];
        g_partials[blockIdx.x] = t;
        __threadfence();                          // partial visible before arrival
        int old = atomicAdd(&g_count, 1);
        s_is_last = (old == nblocks - 1);
    }
    __syncthreads();

    // ---- Last-arriving block: final deterministic reduce ----
    if (s_is_last) {
        __shared__ double sd[THREADS];
        double acc = 0.0;
#pragma unroll
        for (int j = 0; j < NBLOCKS / THREADS; j++)     // 8 iterations, fixed order
            acc += (double)g_partials[threadIdx.x + j * THREADS];
        sd[threadIdx.x] = acc;
        __syncthreads();
        for (int o = THREADS / 2; o; o >>= 1) {
            if (threadIdx.x < o) sd[threadIdx.x] += sd[threadIdx.x + o];
            __syncthreads();
        }
        if (threadIdx.x == 0) {
            out[0] = (float)(0.1 * sd[0]);
            g_count = 0;                          // self-reset for next replay
        }
    }
}

extern "C" void kernel_launch(void* const* d_in, const int* in_sizes, int n_in,
                              void* d_out, int out_size)
{
    const float* in = (const float*)d_in[0];
    const float* tg = (const float*)d_in[1];
    float* out = (float*)d_out;

    qfd_fused<<<NBLOCKS, THREADS>>>(in, tg, out, NBLOCKS);
}